// round 9
// baseline (speedup 1.0000x reference)
#include <cuda_runtime.h>
#include <cuda_bf16.h>
#include <cstdint>

// QuantizedEmbedding: out[i, d] = code[quant_weight[x[i], d]] * absmax[x[i] >> 2]
//   x: int32[16384]  qw: int32[50304,1024]  absmax: f32[12576]  code: f32[256]
//   out: f32[16384,1024]   (block index == v>>2 since (v%4)*1024 + d < 4096)
//
// R9: stores go through TMA (cp.async.bulk 1D, smem->global, evict_first L2
// policy) instead of per-thread STG.128 — removes all store wavefronts and
// STG issue cost from the SM pipes. Double-buffered 4KB staging per token.
// Lane-private codebook (zero LDS conflicts), front-batched 8 LDG.128/thread.

#define TOK 8

__device__ __forceinline__ uint32_t smem_u32(const void* p) {
    uint32_t a;
    asm("{ .reg .u64 t; cvta.to.shared.u64 t, %1; cvt.u32.u64 %0, t; }"
        : "=r"(a) : "l"(p));
    return a;
}

__global__ void __launch_bounds__(256, 4)
qembed_kernel(const int* __restrict__ x,
              const int4* __restrict__ qw,
              const float* __restrict__ absmax,
              const float* __restrict__ code,
              float* __restrict__ out)
{
    __shared__ float s_code[256 * 32];                 // lane-private, 32 KB
    __shared__ __align__(16) float s_out[2][1024];     // 2 x 4 KB staging
    const int t    = threadIdx.x;
    const int lane = t & 31;
    const int tok0 = blockIdx.x * TOK;

    // Front-batch all 8 independent row-chunk loads (MLP = 8/thread).
    int4  q[TOK];
    float sc[TOK];
    #pragma unroll
    for (int k = 0; k < TOK; k++) {
        const int v = x[tok0 + k];
        q[k]  = qw[(size_t)v * 256 + t];
        sc[k] = __ldg(&absmax[v >> 2]);
    }

    // Fill codebook while loads are in flight: word i -> bank i%32, conflict-free.
    #pragma unroll 8
    for (int i = t; i < 256 * 32; i += 256)
        s_code[i] = code[i >> 5];
    __syncthreads();

    uint64_t policy;
    asm volatile("createpolicy.fractional.L2::evict_first.b64 %0, 1.0;" : "=l"(policy));

    #pragma unroll
    for (int k = 0; k < TOK; k++) {
        const int buf = k & 1;

        if (k >= 2) {
            // Reuse staging buffer only after its TMA store has read it.
            if (t == 0)
                asm volatile("cp.async.bulk.wait_group.read 1;" ::: "memory");
            __syncthreads();
        }

        float4 o;
        o.x = s_code[q[k].x * 32 + lane] * sc[k];
        o.y = s_code[q[k].y * 32 + lane] * sc[k];
        o.z = s_code[q[k].z * 32 + lane] * sc[k];
        o.w = s_code[q[k].w * 32 + lane] * sc[k];
        *(float4*)&s_out[buf][t * 4] = o;              // conflict-free STS.128
        __syncthreads();

        if (t == 0) {
            asm volatile("fence.proxy.async;" ::: "memory");
            const float* g = out + (size_t)(tok0 + k) * 1024;
            const uint32_t saddr = smem_u32(&s_out[buf][0]);
            asm volatile(
                "cp.async.bulk.global.shared::cta.bulk_group.L2::cache_hint "
                "[%0], [%1], %2, %3;"
                :: "l"(g), "r"(saddr), "r"(4096), "l"(policy) : "memory");
            asm volatile("cp.async.bulk.commit_group;" ::: "memory");
        }
    }

    // Drain outstanding stores before exit.
    if (t == 0)
        asm volatile("cp.async.bulk.wait_group 0;" ::: "memory");
}

extern "C" void kernel_launch(void* const* d_in, const int* in_sizes, int n_in,
                              void* d_out, int out_size)
{
    // Bind inputs by element count (all four distinct) — robust to ordering.
    const int*   x      = nullptr;  int n_tokens = 0;
    const int4*  qw     = nullptr;
    const float* absmax = nullptr;
    const float* code   = nullptr;

    for (int i = 0; i < n_in; i++) {
        const int sz = in_sizes[i];
        if (sz == 256)            code   = (const float*)d_in[i];
        else if (sz == 12576)     absmax = (const float*)d_in[i];
        else if (sz > 1000000)    qw     = (const int4*)d_in[i];
        else                      { x = (const int*)d_in[i]; n_tokens = sz; }
    }

    float* out = (float*)d_out;
    const int n_cta = n_tokens / TOK;   // 2048
    qembed_kernel<<<n_cta, 256>>>(x, qw, absmax, code, out);
}

// round 10
// speedup vs baseline: 1.5295x; 1.5295x over previous
#include <cuda_runtime.h>
#include <cuda_bf16.h>
#include <cstdint>

// QuantizedEmbedding: out[i, d] = code[quant_weight[x[i], d]] * absmax[x[i] >> 2]
//   x: int32[16384]  qw: int32[50304,1024]  absmax: f32[12576]  code: f32[256]
//   out: f32[16384,1024]   (block index == v>>2 since (v%4)*1024 + d < 4096)
//
// R10: warp-autonomous TMA stores. Each warp dequantizes ONE full 4KB output
// row into a warp-private staging buffer and ships it with a single
// cp.async.bulk (evict_first) — no STG.128 issue cost (12cyc/warp-store, the
// largest MIO term), and ZERO block-wide syncs in the mainloop (R9's poison).
// Front-batched 8x LDG.128/thread; 16-way interleaved codebook (16KB,
// conflict ~1.5, cheap fill). smem 48KB -> occ 4.

__device__ __forceinline__ uint32_t smem_u32(const void* p) {
    uint32_t a;
    asm("{ .reg .u64 t; cvta.to.shared.u64 t, %1; cvt.u32.u64 %0, t; }"
        : "=r"(a) : "l"(p));
    return a;
}

__global__ void __launch_bounds__(256, 4)
qembed_kernel(const int* __restrict__ x,
              const int4* __restrict__ qw,
              const float* __restrict__ absmax,
              const float* __restrict__ code,
              float* __restrict__ out)
{
    __shared__ float s_code[256 * 16];                    // 16 KB, 16-way interleave
    __shared__ __align__(16) float s_stage[8][1024];      // 4 KB per warp
    const int t    = threadIdx.x;
    const int warp = t >> 5;
    const int lane = t & 31;

    const int tok = blockIdx.x * 8 + warp;                // one row per warp
    const int v   = x[tok];
    const float scv = __ldg(&absmax[v >> 2]);

    // Front-batch the warp's entire row: 8 independent coalesced LDG.128.
    int4 q[8];
    #pragma unroll
    for (int i = 0; i < 8; i++)
        q[i] = qw[(size_t)v * 256 + i * 32 + lane];

    // Fill 16-way interleaved codebook while loads are in flight.
    #pragma unroll
    for (int i = t; i < 256 * 16; i += 256)
        s_code[i] = code[i >> 4];
    __syncthreads();                                      // only block sync

    const int c = lane & 15;
    #pragma unroll
    for (int i = 0; i < 8; i++) {
        float4 o;
        o.x = s_code[q[i].x * 16 + c] * scv;
        o.y = s_code[q[i].y * 16 + c] * scv;
        o.z = s_code[q[i].z * 16 + c] * scv;
        o.w = s_code[q[i].w * 16 + c] * scv;
        *(float4*)&s_stage[warp][(i * 32 + lane) * 4] = o;   // conflict-free STS.128
    }
    __syncwarp();

    if (lane == 0) {
        uint64_t policy;
        asm volatile("createpolicy.fractional.L2::evict_first.b64 %0, 1.0;"
                     : "=l"(policy));
        asm volatile("fence.proxy.async;" ::: "memory");
        const float* g = out + (size_t)tok * 1024;
        const uint32_t saddr = smem_u32(&s_stage[warp][0]);
        asm volatile(
            "cp.async.bulk.global.shared::cta.bulk_group.L2::cache_hint "
            "[%0], [%1], %2, %3;"
            :: "l"(g), "r"(saddr), "r"(4096), "l"(policy) : "memory");
        asm volatile("cp.async.bulk.commit_group;" ::: "memory");
        // Hold smem alive until TMA has read the staging buffer.
        asm volatile("cp.async.bulk.wait_group.read 0;" ::: "memory");
    }
}

extern "C" void kernel_launch(void* const* d_in, const int* in_sizes, int n_in,
                              void* d_out, int out_size)
{
    // Bind inputs by element count (all four distinct) — robust to ordering.
    const int*   x      = nullptr;  int n_tokens = 0;
    const int4*  qw     = nullptr;
    const float* absmax = nullptr;
    const float* code   = nullptr;

    for (int i = 0; i < n_in; i++) {
        const int sz = in_sizes[i];
        if (sz == 256)            code   = (const float*)d_in[i];
        else if (sz == 12576)     absmax = (const float*)d_in[i];
        else if (sz > 1000000)    qw     = (const int4*)d_in[i];
        else                      { x = (const int*)d_in[i]; n_tokens = sz; }
    }

    float* out = (float*)d_out;
    const int n_cta = n_tokens / 8;   // 2048 CTAs, 8 rows each (one per warp)
    qembed_kernel<<<n_cta, 256>>>(x, qw, absmax, code, out);
}

// round 11
// speedup vs baseline: 1.9746x; 1.2910x over previous
#include <cuda_runtime.h>
#include <cuda_bf16.h>
#include <cstdint>

// QuantizedEmbedding: out[i, d] = code[quant_weight[x[i], d]] * absmax[x[i] >> 2]
//   x: int32[16384]  qw: int32[50304,1024]  absmax: f32[12576]  code: f32[256]
//   out: f32[16384,1024]   (block index == v>>2 since (v%4)*1024 + d < 4096)
//
// R11 = R5 (best measured: persistent CTAs, double-buffered group prefetch,
// 8-way interleaved codebook, streaming STG) + ONE change: qw reads use
// ld.global.cg (__ldcg) to bypass L1. The gathered rows have ~zero L1 hit
// rate, so L1 allocation/fill was pure overhead in the busiest pipe (L1=55%).

#define TOK 4

__global__ void __launch_bounds__(256, 4)
qembed_kernel(const int* __restrict__ x,
              const int4* __restrict__ qw,
              const float* __restrict__ absmax,
              const float* __restrict__ code,
              float4* __restrict__ out,
              int n_groups)
{
    __shared__ float s_code[256 * 8];
    const int t = threadIdx.x;
    const int c = t & 7;               // lane class -> private 4-bank set

    {
        const float cv = code[t];
        #pragma unroll
        for (int r = 0; r < 8; r++)
            s_code[t * 8 + r] = cv;
    }
    __syncthreads();

    const int G = gridDim.x;
    int g = blockIdx.x;

    // Prefetch first group (qw via L1-bypass loads).
    int4  q[TOK];
    float sc[TOK];
    #pragma unroll
    for (int k = 0; k < TOK; k++) {
        const int v = x[g * TOK + k];
        q[k]  = __ldcg(&qw[(size_t)v * 256 + t]);
        sc[k] = __ldg(&absmax[v >> 2]);
    }

    while (true) {
        const int gn = g + G;

        int4  qn[TOK];
        float scn[TOK];
        if (gn < n_groups) {
            // Issue next group's independent loads before processing current.
            #pragma unroll
            for (int k = 0; k < TOK; k++) {
                const int v = x[gn * TOK + k];
                qn[k]  = __ldcg(&qw[(size_t)v * 256 + t]);
                scn[k] = __ldg(&absmax[v >> 2]);
            }
        }

        // Process current group (LDS lookups + streaming stores).
        #pragma unroll
        for (int k = 0; k < TOK; k++) {
            float4 o;
            o.x = s_code[q[k].x * 8 + c] * sc[k];
            o.y = s_code[q[k].y * 8 + c] * sc[k];
            o.z = s_code[q[k].z * 8 + c] * sc[k];
            o.w = s_code[q[k].w * 8 + c] * sc[k];
            __stcs(&out[(size_t)(g * TOK + k) * 256 + t], o);
        }

        if (gn >= n_groups) break;
        g = gn;
        #pragma unroll
        for (int k = 0; k < TOK; k++) { q[k] = qn[k]; sc[k] = scn[k]; }
    }
}

extern "C" void kernel_launch(void* const* d_in, const int* in_sizes, int n_in,
                              void* d_out, int out_size)
{
    // Bind inputs by element count (all four distinct) — robust to ordering.
    const int*   x      = nullptr;  int n_tokens = 0;
    const int4*  qw     = nullptr;
    const float* absmax = nullptr;
    const float* code   = nullptr;

    for (int i = 0; i < n_in; i++) {
        const int sz = in_sizes[i];
        if (sz == 256)            code   = (const float*)d_in[i];
        else if (sz == 12576)     absmax = (const float*)d_in[i];
        else if (sz > 1000000)    qw     = (const int4*)d_in[i];
        else                      { x = (const int*)d_in[i]; n_tokens = sz; }
    }

    float4* out = (float4*)d_out;
    const int n_groups = n_tokens / TOK;         // 4096
    const int grid = 148 * 4;                    // persistent: one wave at occ 4
    qembed_kernel<<<grid, 256>>>(x, qw, absmax, code, out, n_groups);
}